// round 7
// baseline (speedup 1.0000x reference)
#include <cuda_runtime.h>
#include <cuda_fp16.h>
#include <cstdint>

#define NUM_USERS 100000
#define NUM_ITEMS 50000
#define N_NODES   150000
#define EMB_D     64
#define NUM_EDGES 2000000
#define N_DIRECTED (2 * NUM_EDGES)          // 4M adjacency entries

#define N_HALF2  (N_NODES * (EMB_D / 2))    // 4.8M half2 per buffer
#define SCAN_TILE 1024
#define N_TILES ((N_NODES + SCAN_TILE - 1) / SCAN_TILE)  // 147

// Scratch (device globals; no allocation allowed).
// Node embeddings in fp16: one row = 64 halfs = 128B = one L2 line.
__device__ __half2 g_buf0h[N_HALF2];        // 19.2 MB, concat(user,item)
__device__ __half2 g_buf1h[N_HALF2];        // 19.2 MB, layer-1 output
__device__ int     g_deg[N_NODES];
__device__ int     g_off[N_NODES];
__device__ int     g_cursor[N_NODES];
__device__ int     g_tilesum[N_TILES];
__device__ int     g_adj[N_DIRECTED];       // 16 MB

// ---------------------------------------------------------------------------
// init: buf0h = half(concat(user, item)); deg = 0.
// One thread per float4 (= two half2).
// ---------------------------------------------------------------------------
__global__ void init_kernel(const float4* __restrict__ user4,
                            const float4* __restrict__ item4) {
    const int total4 = N_NODES * (EMB_D / 4);      // 2.4M
    const int user4n = NUM_USERS * (EMB_D / 4);    // 1.6M
    int i = blockIdx.x * blockDim.x + threadIdx.x;
    if (i < total4) {
        float4 v = (i < user4n) ? user4[i] : item4[i - user4n];
        g_buf0h[2 * i + 0] = __floats2half2_rn(v.x, v.y);
        g_buf0h[2 * i + 1] = __floats2half2_rn(v.z, v.w);
    }
    if (i < N_NODES) g_deg[i] = 0;
}

// degree histogram over both edge endpoints
__global__ void hist_kernel(const int* __restrict__ erow,
                            const int* __restrict__ ecol) {
    int e = blockIdx.x * blockDim.x + threadIdx.x;
    if (e >= NUM_EDGES) return;
    atomicAdd(&g_deg[erow[e]], 1);
    atomicAdd(&g_deg[ecol[e]], 1);
}

// exclusive scan, phase A: per-tile scan + tile sums
__global__ void scanA_kernel() {
    __shared__ int sh[SCAN_TILE];
    int t = threadIdx.x;
    int gid = blockIdx.x * SCAN_TILE + t;
    int v = (gid < N_NODES) ? g_deg[gid] : 0;
    sh[t] = v;
    __syncthreads();
    for (int ofs = 1; ofs < SCAN_TILE; ofs <<= 1) {
        int x = (t >= ofs) ? sh[t - ofs] : 0;
        __syncthreads();
        sh[t] += x;
        __syncthreads();
    }
    int incl = sh[t];
    if (gid < N_NODES) g_off[gid] = incl - v;          // exclusive within tile
    if (t == SCAN_TILE - 1) g_tilesum[blockIdx.x] = incl;
}

// phase B: exclusive scan of tile sums (single block; N_TILES <= 256)
__global__ void scanB_kernel() {
    __shared__ int sh[256];
    int t = threadIdx.x;
    int v = (t < N_TILES) ? g_tilesum[t] : 0;
    sh[t] = v;
    __syncthreads();
    for (int ofs = 1; ofs < 256; ofs <<= 1) {
        int x = (t >= ofs) ? sh[t - ofs] : 0;
        __syncthreads();
        sh[t] += x;
        __syncthreads();
    }
    if (t < N_TILES) g_tilesum[t] = sh[t] - v;         // exclusive
}

// phase C: add tile base, init fill cursors
__global__ void scanC_kernel() {
    int gid = blockIdx.x * blockDim.x + threadIdx.x;
    if (gid >= N_NODES) return;
    int o = g_off[gid] + g_tilesum[gid / SCAN_TILE];
    g_off[gid] = o;
    g_cursor[gid] = o;
}

// CSR fill: adjacency of both directions
__global__ void fill_kernel(const int* __restrict__ erow,
                            const int* __restrict__ ecol) {
    int e = blockIdx.x * blockDim.x + threadIdx.x;
    if (e >= NUM_EDGES) return;
    int r = erow[e], c = ecol[e];
    g_adj[atomicAdd(&g_cursor[r], 1)] = c;
    g_adj[atomicAdd(&g_cursor[c], 1)] = r;
}

// ---------------------------------------------------------------------------
// pull layer 1: buf1h[v] = half( 0.5 * sum_{u in adj(v)} buf0h[u] )
// One warp per node; lane owns one half2 column (row = 32 half2 = 128B line).
// fp32 accumulation; 8-way unrolled for MLP.
// ---------------------------------------------------------------------------
__global__ void pull1_kernel() {
    int gwarp = (blockIdx.x * blockDim.x + threadIdx.x) >> 5;
    if (gwarp >= N_NODES) return;
    int lane = threadIdx.x & 31;
    const __half2* __restrict__ src = g_buf0h;

    int start = g_off[gwarp];
    int d     = g_deg[gwarp];

    float ax = 0.f, ay = 0.f;
    int j = 0;
    for (; j + 8 <= d; j += 8) {
        int u0 = g_adj[start + j + 0];
        int u1 = g_adj[start + j + 1];
        int u2 = g_adj[start + j + 2];
        int u3 = g_adj[start + j + 3];
        int u4 = g_adj[start + j + 4];
        int u5 = g_adj[start + j + 5];
        int u6 = g_adj[start + j + 6];
        int u7 = g_adj[start + j + 7];
        float2 a0 = __half22float2(src[(size_t)u0 * 32 + lane]);
        float2 a1 = __half22float2(src[(size_t)u1 * 32 + lane]);
        float2 a2 = __half22float2(src[(size_t)u2 * 32 + lane]);
        float2 a3 = __half22float2(src[(size_t)u3 * 32 + lane]);
        float2 a4 = __half22float2(src[(size_t)u4 * 32 + lane]);
        float2 a5 = __half22float2(src[(size_t)u5 * 32 + lane]);
        float2 a6 = __half22float2(src[(size_t)u6 * 32 + lane]);
        float2 a7 = __half22float2(src[(size_t)u7 * 32 + lane]);
        ax += ((a0.x + a1.x) + (a2.x + a3.x)) + ((a4.x + a5.x) + (a6.x + a7.x));
        ay += ((a0.y + a1.y) + (a2.y + a3.y)) + ((a4.y + a5.y) + (a6.y + a7.y));
    }
    for (; j < d; j++) {
        int u = g_adj[start + j];
        float2 a = __half22float2(src[(size_t)u * 32 + lane]);
        ax += a.x;
        ay += a.y;
    }
    g_buf1h[(size_t)gwarp * 32 + lane] = __floats2half2_rn(0.5f * ax, 0.5f * ay);
}

// ---------------------------------------------------------------------------
// pull layer 2: out[v] = 0.5 * sum_{u in adj(v)} buf1h[u]   (f32 output)
// ---------------------------------------------------------------------------
__global__ void pull2_kernel(float2* __restrict__ out) {
    int gwarp = (blockIdx.x * blockDim.x + threadIdx.x) >> 5;
    if (gwarp >= N_NODES) return;
    int lane = threadIdx.x & 31;
    const __half2* __restrict__ src = g_buf1h;

    int start = g_off[gwarp];
    int d     = g_deg[gwarp];

    float ax = 0.f, ay = 0.f;
    int j = 0;
    for (; j + 8 <= d; j += 8) {
        int u0 = g_adj[start + j + 0];
        int u1 = g_adj[start + j + 1];
        int u2 = g_adj[start + j + 2];
        int u3 = g_adj[start + j + 3];
        int u4 = g_adj[start + j + 4];
        int u5 = g_adj[start + j + 5];
        int u6 = g_adj[start + j + 6];
        int u7 = g_adj[start + j + 7];
        float2 a0 = __half22float2(src[(size_t)u0 * 32 + lane]);
        float2 a1 = __half22float2(src[(size_t)u1 * 32 + lane]);
        float2 a2 = __half22float2(src[(size_t)u2 * 32 + lane]);
        float2 a3 = __half22float2(src[(size_t)u3 * 32 + lane]);
        float2 a4 = __half22float2(src[(size_t)u4 * 32 + lane]);
        float2 a5 = __half22float2(src[(size_t)u5 * 32 + lane]);
        float2 a6 = __half22float2(src[(size_t)u6 * 32 + lane]);
        float2 a7 = __half22float2(src[(size_t)u7 * 32 + lane]);
        ax += ((a0.x + a1.x) + (a2.x + a3.x)) + ((a4.x + a5.x) + (a6.x + a7.x));
        ay += ((a0.y + a1.y) + (a2.y + a3.y)) + ((a4.y + a5.y) + (a6.y + a7.y));
    }
    for (; j < d; j++) {
        int u = g_adj[start + j];
        float2 a = __half22float2(src[(size_t)u * 32 + lane]);
        ax += a.x;
        ay += a.y;
    }
    out[(size_t)gwarp * 32 + lane] = make_float2(0.5f * ax, 0.5f * ay);
}

// ---------------------------------------------------------------------------
extern "C" void kernel_launch(void* const* d_in, const int* in_sizes, int n_in,
                              void* d_out, int out_size) {
    const int*   edge_index = (const int*)d_in[0];   // [2, E] int32
    const float* user_emb   = (const float*)d_in[1];
    const float* item_emb   = (const float*)d_in[2];
    float2*      out2       = (float2*)d_out;

    const int* erow = edge_index;
    const int* ecol = edge_index + NUM_EDGES;

    // init (convert-copy concat + zero degrees)
    {
        const int total4 = N_NODES * (EMB_D / 4);
        init_kernel<<<(total4 + 255) / 256, 256>>>(
            (const float4*)user_emb, (const float4*)item_emb);
    }

    // CSR build
    hist_kernel<<<(NUM_EDGES + 255) / 256, 256>>>(erow, ecol);
    scanA_kernel<<<N_TILES, SCAN_TILE>>>();
    scanB_kernel<<<1, 256>>>();
    scanC_kernel<<<(N_NODES + 255) / 256, 256>>>();
    fill_kernel<<<(NUM_EDGES + 255) / 256, 256>>>(erow, ecol);

    // two pull layers (warp per node)
    {
        long long total_threads = (long long)N_NODES * 32;
        int threads = 256;
        int blocks  = (int)((total_threads + threads - 1) / threads);
        pull1_kernel<<<blocks, threads>>>();
        pull2_kernel<<<blocks, threads>>>(out2);
    }
}

// round 8
// speedup vs baseline: 1.3616x; 1.3616x over previous
#include <cuda_runtime.h>
#include <cuda_fp16.h>
#include <cstdint>

#define NUM_USERS 100000
#define NUM_ITEMS 50000
#define N_NODES   150000
#define EMB_D     64
#define NUM_EDGES 2000000
#define N_DIRECTED (2 * NUM_EDGES)          // 4M adjacency entries

#define N_HALF2  (N_NODES * (EMB_D / 2))    // 4.8M half2 per buffer
#define SCAN_TILE 1024
#define N_TILES ((N_NODES + SCAN_TILE - 1) / SCAN_TILE)  // 147

// Scratch (device globals; no allocation allowed).
// Node embeddings in fp16: one row = 64 halfs = 128B = one L2 line.
__device__ __half2 g_buf0h[N_HALF2];        // 19.2 MB, concat(user,item)
__device__ __half2 g_buf1h[N_HALF2];        // 19.2 MB, layer-1 output
__device__ int     g_deg[N_NODES];
__device__ int     g_off[N_NODES];
__device__ int     g_cursor[N_NODES];
__device__ int     g_tilesum[N_TILES];
__device__ int     g_adj[N_DIRECTED];       // 16 MB

// ---------------------------------------------------------------------------
// init: buf0h = half(concat(user, item)); deg = 0.
// ---------------------------------------------------------------------------
__global__ void init_kernel(const float4* __restrict__ user4,
                            const float4* __restrict__ item4) {
    const int total4 = N_NODES * (EMB_D / 4);      // 2.4M
    const int user4n = NUM_USERS * (EMB_D / 4);    // 1.6M
    int i = blockIdx.x * blockDim.x + threadIdx.x;
    if (i < total4) {
        float4 v = (i < user4n) ? user4[i] : item4[i - user4n];
        g_buf0h[2 * i + 0] = __floats2half2_rn(v.x, v.y);
        g_buf0h[2 * i + 1] = __floats2half2_rn(v.z, v.w);
    }
    if (i < N_NODES) g_deg[i] = 0;
}

// degree histogram over both edge endpoints
__global__ void hist_kernel(const int* __restrict__ erow,
                            const int* __restrict__ ecol) {
    int e = blockIdx.x * blockDim.x + threadIdx.x;
    if (e >= NUM_EDGES) return;
    atomicAdd(&g_deg[erow[e]], 1);
    atomicAdd(&g_deg[ecol[e]], 1);
}

// exclusive scan, phase A: per-tile scan + tile sums
__global__ void scanA_kernel() {
    __shared__ int sh[SCAN_TILE];
    int t = threadIdx.x;
    int gid = blockIdx.x * SCAN_TILE + t;
    int v = (gid < N_NODES) ? g_deg[gid] : 0;
    sh[t] = v;
    __syncthreads();
    for (int ofs = 1; ofs < SCAN_TILE; ofs <<= 1) {
        int x = (t >= ofs) ? sh[t - ofs] : 0;
        __syncthreads();
        sh[t] += x;
        __syncthreads();
    }
    int incl = sh[t];
    if (gid < N_NODES) g_off[gid] = incl - v;          // exclusive within tile
    if (t == SCAN_TILE - 1) g_tilesum[blockIdx.x] = incl;
}

// phase B: exclusive scan of tile sums (single block; N_TILES <= 256)
__global__ void scanB_kernel() {
    __shared__ int sh[256];
    int t = threadIdx.x;
    int v = (t < N_TILES) ? g_tilesum[t] : 0;
    sh[t] = v;
    __syncthreads();
    for (int ofs = 1; ofs < 256; ofs <<= 1) {
        int x = (t >= ofs) ? sh[t - ofs] : 0;
        __syncthreads();
        sh[t] += x;
        __syncthreads();
    }
    if (t < N_TILES) g_tilesum[t] = sh[t] - v;         // exclusive
}

// phase C: add tile base, init fill cursors
__global__ void scanC_kernel() {
    int gid = blockIdx.x * blockDim.x + threadIdx.x;
    if (gid >= N_NODES) return;
    int o = g_off[gid] + g_tilesum[gid / SCAN_TILE];
    g_off[gid] = o;
    g_cursor[gid] = o;
}

// CSR fill: adjacency of both directions
__global__ void fill_kernel(const int* __restrict__ erow,
                            const int* __restrict__ ecol) {
    int e = blockIdx.x * blockDim.x + threadIdx.x;
    if (e >= NUM_EDGES) return;
    int r = erow[e], c = ecol[e];
    g_adj[atomicAdd(&g_cursor[r], 1)] = c;
    g_adj[atomicAdd(&g_cursor[c], 1)] = r;
}

// ---------------------------------------------------------------------------
// Shared pull body: acc = sum_{u in adj(v)} src[u][lane-pair], fp32 accum.
// Unroll 16: 16 outstanding 128B row-gathers per warp (2 KB in flight) so
// the fp16 (single-line) gathers stay concurrency-saturated, not
// latency-bound. Gather into a register array first, then reduce.
// ---------------------------------------------------------------------------
__device__ __forceinline__ float2 pull_row(const __half2* __restrict__ src,
                                           int start, int d, int lane) {
    float ax = 0.f, ay = 0.f;
    int j = 0;
    for (; j + 16 <= d; j += 16) {
        float2 s[16];
#pragma unroll
        for (int k = 0; k < 16; k++) {
            int u = g_adj[start + j + k];
            s[k] = __half22float2(src[(size_t)u * 32 + lane]);
        }
#pragma unroll
        for (int k = 0; k < 16; k++) {
            ax += s[k].x;
            ay += s[k].y;
        }
    }
    for (; j + 4 <= d; j += 4) {
        float2 s[4];
#pragma unroll
        for (int k = 0; k < 4; k++) {
            int u = g_adj[start + j + k];
            s[k] = __half22float2(src[(size_t)u * 32 + lane]);
        }
#pragma unroll
        for (int k = 0; k < 4; k++) {
            ax += s[k].x;
            ay += s[k].y;
        }
    }
    for (; j < d; j++) {
        int u = g_adj[start + j];
        float2 a = __half22float2(src[(size_t)u * 32 + lane]);
        ax += a.x;
        ay += a.y;
    }
    return make_float2(ax, ay);
}

// pull layer 1: buf1h[v] = half( 0.5 * sum buf0h[adj] )
__global__ void pull1_kernel() {
    int gwarp = (blockIdx.x * blockDim.x + threadIdx.x) >> 5;
    if (gwarp >= N_NODES) return;
    int lane = threadIdx.x & 31;
    float2 a = pull_row(g_buf0h, g_off[gwarp], g_deg[gwarp], lane);
    g_buf1h[(size_t)gwarp * 32 + lane] = __floats2half2_rn(0.5f * a.x, 0.5f * a.y);
}

// pull layer 2: out[v] = 0.5 * sum buf1h[adj]   (f32 output)
__global__ void pull2_kernel(float2* __restrict__ out) {
    int gwarp = (blockIdx.x * blockDim.x + threadIdx.x) >> 5;
    if (gwarp >= N_NODES) return;
    int lane = threadIdx.x & 31;
    float2 a = pull_row(g_buf1h, g_off[gwarp], g_deg[gwarp], lane);
    out[(size_t)gwarp * 32 + lane] = make_float2(0.5f * a.x, 0.5f * a.y);
}

// ---------------------------------------------------------------------------
extern "C" void kernel_launch(void* const* d_in, const int* in_sizes, int n_in,
                              void* d_out, int out_size) {
    const int*   edge_index = (const int*)d_in[0];   // [2, E] int32
    const float* user_emb   = (const float*)d_in[1];
    const float* item_emb   = (const float*)d_in[2];
    float2*      out2       = (float2*)d_out;

    const int* erow = edge_index;
    const int* ecol = edge_index + NUM_EDGES;

    // init (convert-copy concat + zero degrees)
    {
        const int total4 = N_NODES * (EMB_D / 4);
        init_kernel<<<(total4 + 255) / 256, 256>>>(
            (const float4*)user_emb, (const float4*)item_emb);
    }

    // CSR build
    hist_kernel<<<(NUM_EDGES + 255) / 256, 256>>>(erow, ecol);
    scanA_kernel<<<N_TILES, SCAN_TILE>>>();
    scanB_kernel<<<1, 256>>>();
    scanC_kernel<<<(N_NODES + 255) / 256, 256>>>();
    fill_kernel<<<(NUM_EDGES + 255) / 256, 256>>>(erow, ecol);

    // two pull layers (warp per node)
    {
        long long total_threads = (long long)N_NODES * 32;
        int threads = 256;
        int blocks  = (int)((total_threads + threads - 1) / threads);
        pull1_kernel<<<blocks, threads>>>();
        pull2_kernel<<<blocks, threads>>>(out2);
    }
}